// round 1
// baseline (speedup 1.0000x reference)
#include <cuda_runtime.h>

#define Tn   128
#define Cc   256
#define Kk   3
#define Vv   25
#define VP   26      // padded V (13 f32x2 pairs)
#define Gg   9
#define Ll   9
#define NCc  60
#define CINn 3
#define CV   (Cc*Vv) // 6400

// ---------------- device scratch (static: no allocations allowed) ----------------
__device__ float g_H[2][Tn*CV];          // ping-pong layer activations (T,C,V)
__device__ float g_U[Tn*CV];             // u_t = relu(LN1(z_t)) per layer iteration
__device__ float g_Uinit[Ll*CV];         // relu(ln1_b) — value of u for t<0 (zero FIFO)
__device__ float g_Al[Ll*Kk*Vv*Vv];      // A * imp
__device__ float g_WgT[Ll*Cc*Kk*Cc];     // [l][c'][k*C+c]  (transposed for coalescing)
__device__ float g_WtT[Ll*Gg*Cc*Cc];     // [l][g][c'][o]

typedef unsigned long long u64;

__device__ __forceinline__ u64 pk2(float lo, float hi){
    return (u64)__float_as_uint(lo) | ((u64)__float_as_uint(hi) << 32);
}
__device__ __forceinline__ float2 up2(u64 v){
    float2 f;
    f.x = __uint_as_float((unsigned)v);
    f.y = __uint_as_float((unsigned)(v >> 32));
    return f;
}
// packed dual-FMA: d = a*b + d  (2 fp32 MACs / instr)
__device__ __forceinline__ void fma2(u64 &d, u64 a, u64 b){
    asm("fma.rn.f32x2 %0, %1, %2, %0;" : "+l"(d) : "l"(a), "l"(b));
}
__device__ __forceinline__ u64 ld64s(const float* p){
    return *reinterpret_cast<const u64*>(p);
}

// block-wide sum of (a, b); valid for blockDim.x <= 256, returns same value to all threads
__device__ __forceinline__ float2 block_reduce_2(float a, float b){
    __shared__ float redA[8], redB[8];
    int lane = threadIdx.x & 31, w = threadIdx.x >> 5;
    #pragma unroll
    for (int o = 16; o; o >>= 1){
        a += __shfl_xor_sync(0xffffffffu, a, o);
        b += __shfl_xor_sync(0xffffffffu, b, o);
    }
    if (lane == 0){ redA[w] = a; redB[w] = b; }
    __syncthreads();
    int nw = (blockDim.x + 31) >> 5;
    if (w == 0){
        a = (lane < nw) ? redA[lane] : 0.f;
        b = (lane < nw) ? redB[lane] : 0.f;
        #pragma unroll
        for (int o = 4; o; o >>= 1){
            a += __shfl_xor_sync(0xffffffffu, a, o);
            b += __shfl_xor_sync(0xffffffffu, b, o);
        }
        if (lane == 0){ redA[0] = a; redB[0] = b; }
    }
    __syncthreads();
    return make_float2(redA[0], redB[0]);
}

// ---------------- prep kernels ----------------
__global__ void k_prep_wg(const float* __restrict__ Wg){
    int n = Ll*Kk*Cc*Cc;
    for (int idx = blockIdx.x*blockDim.x + threadIdx.x; idx < n; idx += gridDim.x*blockDim.x){
        int l  = idx / (Kk*Cc*Cc);
        int r  = idx - l*(Kk*Cc*Cc);
        int kc = r / Cc;
        int cp = r - kc*Cc;
        g_WgT[(l*Cc + cp)*(Kk*Cc) + kc] = Wg[idx];
    }
}
__global__ void k_prep_wt(const float* __restrict__ Wt){
    int n = Ll*Cc*Cc*Gg;
    for (int idx = blockIdx.x*blockDim.x + threadIdx.x; idx < n; idx += gridDim.x*blockDim.x){
        int l  = idx / (Cc*Cc*Gg);
        int r  = idx - l*(Cc*Cc*Gg);
        int o  = r / (Cc*Gg);
        int r2 = r - o*(Cc*Gg);
        int cp = r2 / Gg;
        int g  = r2 - cp*Gg;
        g_WtT[((l*Gg + g)*Cc + cp)*Cc + o] = Wt[idx];
    }
}
__global__ void k_prep_misc(const float* __restrict__ A, const float* __restrict__ imp,
                            const float* __restrict__ ln1b){
    int n1 = Ll*Kk*Vv*Vv;
    for (int idx = blockIdx.x*blockDim.x + threadIdx.x; idx < n1; idx += gridDim.x*blockDim.x)
        g_Al[idx] = A[idx % (Kk*Vv*Vv)] * imp[idx];
    int n2 = Ll*CV;
    for (int idx = blockIdx.x*blockDim.x + threadIdx.x; idx < n2; idx += gridDim.x*blockDim.x)
        g_Uinit[idx] = fmaxf(ln1b[idx], 0.f);
}

// ---------------- input stage: LN over (CIN,V) + 1x1 conv -> H[0] ----------------
__global__ __launch_bounds__(256,1) void k_in(const float* __restrict__ x,
                                              const float* __restrict__ lnw,
                                              const float* __restrict__ lnb,
                                              const float* __restrict__ Win,
                                              const float* __restrict__ bin){
    __shared__ float sh_xn[CINn*Vv];
    int t = blockIdx.x, tid = threadIdx.x;
    float val = 0.f;
    if (tid < CINn*Vv){
        int cin = tid / Vv, v = tid - cin*Vv;
        val = x[(cin*Tn + t)*Vv + v];
    }
    float2 r = block_reduce_2(val, val*val);
    float m    = r.x * (1.f/75.f);
    float var  = r.y * (1.f/75.f) - m*m;
    float rstd = rsqrtf(var + 1e-5f);
    if (tid < CINn*Vv) sh_xn[tid] = (val - m)*rstd*lnw[tid] + lnb[tid];
    __syncthreads();
    int c = tid;
    float w0 = Win[c*3], w1 = Win[c*3+1], w2 = Win[c*3+2], b = bin[c];
    float* Ho = g_H[0] + t*CV + c*Vv;
    #pragma unroll
    for (int v = 0; v < Vv; v++)
        Ho[v] = b + w0*sh_xn[v] + w1*sh_xn[Vv+v] + w2*sh_xn[2*Vv+v];
}

// ---------------- stage 1 per layer: graph conv + LN1 + relu -> U ----------------
__global__ __launch_bounds__(256,1) void k_g1(const float* __restrict__ bg,
                                              const float* __restrict__ ln1w,
                                              const float* __restrict__ ln1b,
                                              int l, int inbuf){
    __shared__ __align__(16) float sh_h [Cc*VP];
    __shared__ __align__(16) float sh_al[Kk*Vv*VP];
    int t = blockIdx.x, tid = threadIdx.x;
    const float* Hin = g_H[inbuf] + t*CV;
    for (int j = tid; j < CV; j += 256){
        int c = j / Vv, v = j - c*Vv;
        sh_h[c*VP + v] = Hin[j];
    }
    sh_h[tid*VP + 25] = 0.f;   // pad column
    const float* Alp = g_Al + l*(Kk*Vv*Vv);
    for (int j = tid; j < Kk*Vv*VP; j += 256){
        int kv = j / VP, w = j - kv*VP;
        sh_al[j] = (w < Vv) ? Alp[kv*Vv + w] : 0.f;
    }
    __syncthreads();

    int c = tid;
    // y[k][c][v] = sum_c' Wg[l][k*C+c][c'] * h[c'][v]   (bias folded in later)
    u64 y[Kk][13];
    #pragma unroll
    for (int k = 0; k < Kk; k++)
        #pragma unroll
        for (int j = 0; j < 13; j++) y[k][j] = 0ull;

    const float* wg = g_WgT + (l*Cc)*(Kk*Cc) + c;     // + cp*768 + k*256
    for (int cp = 0; cp < Cc; cp++){
        const float* hr = sh_h + cp*VP;
        u64 hp[13];
        #pragma unroll
        for (int j = 0; j < 13; j++) hp[j] = ld64s(hr + 2*j);
        const float* wrow = wg + cp*(Kk*Cc);
        #pragma unroll
        for (int k = 0; k < Kk; k++){
            float wv = wrow[k*Cc];
            u64 wp = pk2(wv, wv);
            #pragma unroll
            for (int j = 0; j < 13; j++) fma2(y[k][j], hp[j], wp);
        }
    }

    // z[c][w] = sum_k sum_v (y + bg) * Al[l][k][v][w]
    u64 zp[13];
    #pragma unroll
    for (int j = 0; j < 13; j++) zp[j] = 0ull;
    #pragma unroll
    for (int k = 0; k < Kk; k++){
        float bgv = bg[(l*Kk + k)*Cc + c];
        #pragma unroll
        for (int j = 0; j < 13; j++){
            float2 yy = up2(y[k][j]);
            int v0 = 2*j;
            {
                float yv = yy.x + bgv;
                u64 yp = pk2(yv, yv);
                const float* al = sh_al + (k*Vv + v0)*VP;
                #pragma unroll
                for (int jw = 0; jw < 13; jw++) fma2(zp[jw], ld64s(al + 2*jw), yp);
            }
            if (v0 + 1 < Vv){
                float yv = yy.y + bgv;
                u64 yp = pk2(yv, yv);
                const float* al = sh_al + (k*Vv + v0 + 1)*VP;
                #pragma unroll
                for (int jw = 0; jw < 13; jw++) fma2(zp[jw], ld64s(al + 2*jw), yp);
            }
        }
    }

    // LN over (C,V), then u = relu(.) -> g_U
    float zs[VP];
    #pragma unroll
    for (int j = 0; j < 13; j++){
        float2 zz = up2(zp[j]);
        zs[2*j] = zz.x; zs[2*j+1] = zz.y;
    }
    float s = 0.f, s2 = 0.f;
    #pragma unroll
    for (int v = 0; v < Vv; v++){ s += zs[v]; s2 += zs[v]*zs[v]; }
    float2 r = block_reduce_2(s, s2);
    float m    = r.x * (1.f/6400.f);
    float var  = r.y * (1.f/6400.f) - m*m;
    float rstd = rsqrtf(var + 1e-5f);

    float* Uo = g_U + t*CV + c*Vv;
    const float* w1 = ln1w + l*CV + c*Vv;
    const float* b1 = ln1b + l*CV + c*Vv;
    #pragma unroll
    for (int v = 0; v < Vv; v++){
        float uv = (zs[v] - m)*rstd*w1[v] + b1[v];
        Uo[v] = fmaxf(uv, 0.f);
    }
}

// ---------------- stage 2 per layer: temporal conv + LN2 + residual + relu -> H ----------------
__global__ __launch_bounds__(256,1) void k_g2(const float* __restrict__ bt,
                                              const float* __restrict__ ln2w,
                                              const float* __restrict__ ln2b,
                                              int l, int inbuf, int outbuf){
    __shared__ __align__(16) float sh_u[Cc*VP];
    int t = blockIdx.x, tid = threadIdx.x;
    sh_u[tid*VP + 25] = 0.f;   // pad column (written once, before first sync)
    int o = tid;
    u64 sp[13];
    #pragma unroll
    for (int j = 0; j < 13; j++) sp[j] = 0ull;

    for (int g = 0; g < Gg; g++){
        const float* src = (t >= g) ? (g_U + (t-g)*CV) : (g_Uinit + l*CV);
        __syncthreads();
        for (int j = tid; j < CV; j += 256){
            int c = j / Vv, v = j - c*Vv;
            sh_u[c*VP + v] = src[j];
        }
        __syncthreads();
        const float* wt = g_WtT + ((l*Gg + g)*Cc)*Cc + o;   // + cp*256
        for (int cp = 0; cp < Cc; cp++){
            float wv = wt[cp*Cc];
            u64 wp = pk2(wv, wv);
            const float* ur = sh_u + cp*VP;
            #pragma unroll
            for (int j = 0; j < 13; j++) fma2(sp[j], ld64s(ur + 2*j), wp);
        }
    }

    float sv[VP];
    #pragma unroll
    for (int j = 0; j < 13; j++){
        float2 ss = up2(sp[j]);
        sv[2*j] = ss.x; sv[2*j+1] = ss.y;
    }
    float btv = bt[l*Cc + o];
    float s = 0.f, s2 = 0.f;
    #pragma unroll
    for (int v = 0; v < Vv; v++){
        sv[v] += btv;
        s += sv[v]; s2 += sv[v]*sv[v];
    }
    float2 r = block_reduce_2(s, s2);
    float m    = r.x * (1.f/6400.f);
    float var  = r.y * (1.f/6400.f) - m*m;
    float rstd = rsqrtf(var + 1e-5f);

    const float* w2  = ln2w + l*CV + o*Vv;
    const float* b2  = ln2b + l*CV + o*Vv;
    const float* res = g_H[inbuf] + (t-4)*CV + o*Vv;   // only read when t>=4
    float* Ho = g_H[outbuf] + t*CV + o*Vv;
    #pragma unroll
    for (int v = 0; v < Vv; v++){
        float val = (sv[v] - m)*rstd*w2[v] + b2[v];
        if (t >= 4) val += res[v];
        Ho[v] = fmaxf(val, 0.f);
    }
}

// ---------------- output head: pool over V + linear ----------------
__global__ void k_out(const float* __restrict__ Wout, const float* __restrict__ bout,
                      float* __restrict__ out, int finbuf){
    __shared__ float pooled[Cc];
    int t = blockIdx.x, tid = threadIdx.x;   // 64 threads
    const float* H = g_H[finbuf] + t*CV;
    for (int c = tid; c < Cc; c += 64){
        float s = 0.f;
        #pragma unroll
        for (int v = 0; v < Vv; v++) s += H[c*Vv + v];
        pooled[c] = s * (1.f/25.f);
    }
    __syncthreads();
    if (tid < NCc){
        float acc = bout[tid];
        const float* wr = Wout + tid*Cc;
        #pragma unroll 8
        for (int c = 0; c < Cc; c++) acc += wr[c]*pooled[c];
        out[t*NCc + tid] = acc;
    }
}

// ---------------- launcher ----------------
extern "C" void kernel_launch(void* const* d_in, const int* in_sizes, int n_in,
                              void* d_out, int out_size){
    const float* x       = (const float*)d_in[0];
    const float* A       = (const float*)d_in[1];
    const float* ln_in_w = (const float*)d_in[2];
    const float* ln_in_b = (const float*)d_in[3];
    const float* W_in    = (const float*)d_in[4];
    const float* b_in    = (const float*)d_in[5];
    const float* Wg      = (const float*)d_in[6];
    const float* bg      = (const float*)d_in[7];
    const float* ln1_w   = (const float*)d_in[8];
    const float* ln1_b   = (const float*)d_in[9];
    const float* Wt      = (const float*)d_in[10];
    const float* bt      = (const float*)d_in[11];
    const float* ln2_w   = (const float*)d_in[12];
    const float* ln2_b   = (const float*)d_in[13];
    const float* imp     = (const float*)d_in[14];
    const float* W_out   = (const float*)d_in[15];
    const float* b_out   = (const float*)d_in[16];
    float* out = (float*)d_out;

    k_prep_wg  <<<512, 256>>>(Wg);
    k_prep_wt  <<<1024,256>>>(Wt);
    k_prep_misc<<<64,  256>>>(A, imp, ln1_b);
    k_in       <<<Tn,  256>>>(x, ln_in_w, ln_in_b, W_in, b_in);

    int inb = 0;
    for (int l = 0; l < Ll; l++){
        k_g1<<<Tn, 256>>>(bg, ln1_w, ln1_b, l, inb);
        k_g2<<<Tn, 256>>>(bt, ln2_w, ln2_b, l, inb, 1 - inb);
        inb = 1 - inb;
    }
    k_out<<<Tn, 64>>>(W_out, b_out, out, inb);
}

// round 7
// speedup vs baseline: 1.5970x; 1.5970x over previous
#include <cuda_runtime.h>

#define Tn   128
#define Cc   256
#define Kk   3
#define Vv   25
#define VP   26      // padded V (13 f32x2 pairs)
#define Gg   9
#define Ll   9
#define NCc  60
#define CINn 3
#define CV   (Cc*Vv)   // 6400
#define CVP  (Cc*VP)   // 6656
#define NPAIR 13

typedef unsigned long long u64;

// ---------------- device scratch (static: no allocations allowed) ----------------
__device__ __align__(16) float g_Hpad[2][Tn*CVP];     // ping-pong activations (t, c, VP)
__device__ __align__(16) float g_Upad[Tn*CVP];        // u_t per layer iteration
__device__ __align__(16) float g_UinitPad[Ll*CVP];    // relu(ln1_b), for t<0
__device__ __align__(16) float g_Al[Ll*Kk*Vv*Vv];     // A * imp
__device__ __align__(16) float g_WgT2[Ll*Cc*Kk*Cc];   // [l][cp][row=k*C+c]
__device__ __align__(16) float g_WtT [Ll*Gg*Cc*Cc];   // [l][g][cp][o]

__device__ __forceinline__ u64 pk2(float lo, float hi){
    return (u64)__float_as_uint(lo) | ((u64)__float_as_uint(hi) << 32);
}
__device__ __forceinline__ float2 up2(u64 v){
    float2 f;
    f.x = __uint_as_float((unsigned)v);
    f.y = __uint_as_float((unsigned)(v >> 32));
    return f;
}
// packed dual-FMA: d = a*b + d
__device__ __forceinline__ void fma2(u64 &d, u64 a, u64 b){
    asm("fma.rn.f32x2 %0, %1, %2, %0;" : "+l"(d) : "l"(a), "l"(b));
}

// block-wide sum of (a,b); up to 16 warps; returns same value to all threads
__device__ __forceinline__ float2 block_reduce_2(float a, float b){
    __shared__ float rA[16], rB[16];
    int lane = threadIdx.x & 31, w = threadIdx.x >> 5;
    #pragma unroll
    for (int o = 16; o; o >>= 1){
        a += __shfl_xor_sync(0xffffffffu, a, o);
        b += __shfl_xor_sync(0xffffffffu, b, o);
    }
    if (lane == 0){ rA[w] = a; rB[w] = b; }
    __syncthreads();
    int nw = blockDim.x >> 5;
    if (w == 0){
        a = (lane < nw) ? rA[lane] : 0.f;
        b = (lane < nw) ? rB[lane] : 0.f;
        #pragma unroll
        for (int o = 8; o; o >>= 1){
            a += __shfl_xor_sync(0xffffffffu, a, o);
            b += __shfl_xor_sync(0xffffffffu, b, o);
        }
        if (lane == 0){ rA[0] = a; rB[0] = b; }
    }
    __syncthreads();
    return make_float2(rA[0], rB[0]);
}

// ---------------- prep kernels ----------------
__global__ void k_prep_wg(const float* __restrict__ Wg){
    int n = Ll*Cc*Kk*Cc;
    for (int d = blockIdx.x*blockDim.x + threadIdx.x; d < n; d += gridDim.x*blockDim.x){
        int l   = d / (Cc*Kk*Cc);
        int r   = d - l*(Cc*Kk*Cc);
        int cp  = r / (Kk*Cc);
        int row = r - cp*(Kk*Cc);
        g_WgT2[d] = Wg[(l*(Kk*Cc) + row)*Cc + cp];
    }
}
__global__ void k_prep_wt(const float* __restrict__ Wt){
    int n = Ll*Gg*Cc*Cc;
    for (int d = blockIdx.x*blockDim.x + threadIdx.x; d < n; d += gridDim.x*blockDim.x){
        int l  = d / (Gg*Cc*Cc);
        int r  = d - l*(Gg*Cc*Cc);
        int g  = r / (Cc*Cc);
        int r2 = r - g*(Cc*Cc);
        int cp = r2 / Cc;
        int o  = r2 - cp*Cc;
        g_WtT[d] = Wt[((l*Cc + o)*Cc + cp)*Gg + g];
    }
}
__global__ void k_prep_misc(const float* __restrict__ A, const float* __restrict__ imp,
                            const float* __restrict__ ln1b){
    int n1 = Ll*Kk*Vv*Vv;
    for (int idx = blockIdx.x*blockDim.x + threadIdx.x; idx < n1; idx += gridDim.x*blockDim.x)
        g_Al[idx] = A[idx % (Kk*Vv*Vv)] * imp[idx];
    int n2 = Ll*CVP;
    for (int idx = blockIdx.x*blockDim.x + threadIdx.x; idx < n2; idx += gridDim.x*blockDim.x){
        int l = idx / CVP;
        int r = idx - l*CVP;
        int c = r / VP, v = r - c*VP;
        g_UinitPad[idx] = (v < Vv) ? fmaxf(ln1b[l*CV + c*Vv + v], 0.f) : 0.f;
    }
}

// ---------------- input stage: LN over (CIN,V) + 1x1 conv -> Hpad[0] ----------------
__global__ __launch_bounds__(256,1) void k_in(const float* __restrict__ x,
                                              const float* __restrict__ lnw,
                                              const float* __restrict__ lnb,
                                              const float* __restrict__ Win,
                                              const float* __restrict__ bin){
    __shared__ float sh_xn[CINn*Vv];
    int t = blockIdx.x, tid = threadIdx.x;
    float val = 0.f;
    if (tid < CINn*Vv){
        int cin = tid / Vv, v = tid - cin*Vv;
        val = x[(cin*Tn + t)*Vv + v];
    }
    float2 r = block_reduce_2(val, val*val);
    float m    = r.x * (1.f/75.f);
    float var  = r.y * (1.f/75.f) - m*m;
    float rstd = rsqrtf(var + 1e-5f);
    if (tid < CINn*Vv) sh_xn[tid] = (val - m)*rstd*lnw[tid] + lnb[tid];
    __syncthreads();
    int c = tid;
    float w0 = Win[c*3], w1 = Win[c*3+1], w2 = Win[c*3+2], b = bin[c];
    float* Ho = g_Hpad[0] + t*CVP + c*VP;
    #pragma unroll
    for (int v = 0; v < Vv; v++)
        Ho[v] = b + w0*sh_xn[v] + w1*sh_xn[Vv+v] + w2*sh_xn[2*Vv+v];
    Ho[Vv] = 0.f;
}

// ---------------- stage 1: graph conv + adjacency + LN1 + relu -> Upad ----------------
// 384 threads: kq = tid/192 splits cp in halves of 128; oq = tid%192 owns rows 4oq..4oq+3
// of the 768 (k*C+c) rows. Static smem: sh_buf (h tile, reused as per-k y buffer) + sh_al.
#define G1_THREADS 384

__global__ __launch_bounds__(G1_THREADS,1) void k_g1(const float* __restrict__ bg,
                                                     const float* __restrict__ ln1w,
                                                     const float* __restrict__ ln1b,
                                                     int l, int inbuf){
    __shared__ __align__(16) u64   sh_buf[CVP/2];       // 3328 u64 = 26,624 B
    __shared__ __align__(16) float sh_al[Kk*Vv*VP];     // 7,800 B

    int t = blockIdx.x, tid = threadIdx.x;
    const u64* Hin = (const u64*)(g_Hpad[inbuf] + t*CVP);
    for (int j = tid; j < CVP/2; j += G1_THREADS) sh_buf[j] = Hin[j];
    const float* Alp = g_Al + l*(Kk*Vv*Vv);
    for (int j = tid; j < Kk*Vv*VP; j += G1_THREADS){
        int kv = j / VP, w = j - kv*VP;
        sh_al[j] = (w < Vv) ? Alp[kv*Vv + w] : 0.f;
    }
    __syncthreads();

    int kq = tid / 192, oq = tid - kq*192;
    u64 acc[4][NPAIR];
    #pragma unroll
    for (int ch = 0; ch < 4; ch++)
        #pragma unroll
        for (int j = 0; j < NPAIR; j++) acc[ch][j] = 0ull;

    const float4* wq = (const float4*)(g_WgT2 + (size_t)(l*Cc + kq*128)*(Kk*Cc)) + oq;
    const u64* hrow = sh_buf + (kq*128)*NPAIR;
    #pragma unroll 2
    for (int cp = 0; cp < 128; cp++){
        u64 hp[NPAIR];
        #pragma unroll
        for (int j = 0; j < NPAIR; j++) hp[j] = hrow[j];
        hrow += NPAIR;
        float4 w = wq[(size_t)cp*192];
        u64 w0 = pk2(w.x,w.x), w1 = pk2(w.y,w.y), w2 = pk2(w.z,w.z), w3 = pk2(w.w,w.w);
        #pragma unroll
        for (int j = 0; j < NPAIR; j++){
            fma2(acc[0][j], hp[j], w0);
            fma2(acc[1][j], hp[j], w1);
            fma2(acc[2][j], hp[j], w2);
            fma2(acc[3][j], hp[j], w3);
        }
    }

    // Per-k batches: combine the two cp-halves of y through sh_buf (reused h region),
    // then apply adjacency for that k into persistent zp registers (threads 0..255).
    int c = tid;             // for adjacency phase
    u64 zp[NPAIR];
    #pragma unroll
    for (int j = 0; j < NPAIR; j++) zp[j] = 0ull;

    #pragma unroll
    for (int k = 0; k < Kk; k++){
        int lo = 64*k, hi = lo + 64;
        __syncthreads();                     // previous phase's reads of sh_buf done
        if (kq == 0 && oq >= lo && oq < hi){
            int cbase = 4*oq - 256*k;
            #pragma unroll
            for (int ch = 0; ch < 4; ch++)
                #pragma unroll
                for (int j = 0; j < NPAIR; j++)
                    sh_buf[(cbase + ch)*NPAIR + j] = acc[ch][j];
        }
        __syncthreads();
        if (kq == 1 && oq >= lo && oq < hi){
            int cbase = 4*oq - 256*k;
            #pragma unroll
            for (int ch = 0; ch < 4; ch++)
                #pragma unroll
                for (int j = 0; j < NPAIR; j++){
                    u64* dst = sh_buf + (cbase + ch)*NPAIR + j;
                    float2 a = up2(acc[ch][j]), b = up2(*dst);
                    *dst = pk2(a.x + b.x, a.y + b.y);
                }
        }
        __syncthreads();
        if (tid < Cc){
            float bgv = bg[(l*Kk + k)*Cc + c];
            const u64* yrow = sh_buf + c*NPAIR;
            #pragma unroll
            for (int jp = 0; jp < NPAIR; jp++){
                float2 yy = up2(yrow[jp]);
                int v0 = 2*jp;
                {
                    float yv = yy.x + bgv;
                    u64 yp = pk2(yv, yv);
                    const u64* al = (const u64*)(sh_al + (k*Vv + v0)*VP);
                    #pragma unroll
                    for (int jw = 0; jw < NPAIR; jw++) fma2(zp[jw], al[jw], yp);
                }
                if (v0 + 1 < Vv){
                    float yv = yy.y + bgv;
                    u64 yp = pk2(yv, yv);
                    const u64* al = (const u64*)(sh_al + (k*Vv + v0 + 1)*VP);
                    #pragma unroll
                    for (int jw = 0; jw < NPAIR; jw++) fma2(zp[jw], al[jw], yp);
                }
            }
        }
    }

    // LN over (C,V), relu -> Upad
    float s = 0.f, s2 = 0.f;
    float zs[VP];
    if (tid < Cc){
        #pragma unroll
        for (int j = 0; j < NPAIR; j++){
            float2 zz = up2(zp[j]);
            zs[2*j] = zz.x; zs[2*j+1] = zz.y;
        }
        #pragma unroll
        for (int v = 0; v < Vv; v++){ s += zs[v]; s2 += zs[v]*zs[v]; }
    }
    float2 r = block_reduce_2(s, s2);
    float m    = r.x * (1.f/6400.f);
    float var  = r.y * (1.f/6400.f) - m*m;
    float rstd = rsqrtf(var + 1e-5f);
    if (tid < Cc){
        float* Uo = g_Upad + t*CVP + c*VP;
        const float* w1 = ln1w + l*CV + c*Vv;
        const float* b1 = ln1b + l*CV + c*Vv;
        #pragma unroll
        for (int v = 0; v < Vv; v++)
            Uo[v] = fmaxf((zs[v] - m)*rstd*w1[v] + b1[v], 0.f);
        Uo[Vv] = 0.f;
    }
}

// ---------------- stage 2: temporal conv + LN2 + residual + relu -> Hpad ----------------
// 512 threads: kq = tid>>7 splits cp in quarters of 64; oq = tid&127 owns o = 2oq, 2oq+1.
// Static smem: sh_buf holds the u tile during the main loop, then is reused one quarter
// at a time as the partial-reduction buffer (128*2*13 = 3328 u64 = exactly the tile size).
#define G2_THREADS 512

__global__ __launch_bounds__(G2_THREADS,1) void k_g2(const float* __restrict__ bt,
                                                     const float* __restrict__ ln2w,
                                                     const float* __restrict__ ln2b,
                                                     int l, int inbuf, int outbuf){
    __shared__ __align__(16) u64 sh_buf[CVP/2];   // 3328 u64 = 26,624 B

    int t = blockIdx.x, tid = threadIdx.x;
    int kq = tid >> 7, oq = tid & 127;
    u64 acc[2][NPAIR];
    #pragma unroll
    for (int ch = 0; ch < 2; ch++)
        #pragma unroll
        for (int j = 0; j < NPAIR; j++) acc[ch][j] = 0ull;

    for (int g = 0; g < Gg; g++){
        const u64* src = (t >= g) ? (const u64*)(g_Upad + (t-g)*CVP)
                                  : (const u64*)(g_UinitPad + l*CVP);
        __syncthreads();
        for (int j = tid; j < CVP/2; j += G2_THREADS) sh_buf[j] = src[j];
        __syncthreads();

        const float2* wq = (const float2*)(g_WtT + (size_t)((l*Gg + g)*Cc + kq*64)*Cc) + oq;
        const u64* urow = sh_buf + (kq*64)*NPAIR;
        #pragma unroll 2
        for (int cp = 0; cp < 64; cp++){
            u64 hp[NPAIR];
            #pragma unroll
            for (int j = 0; j < NPAIR; j++) hp[j] = urow[j];
            urow += NPAIR;
            float2 w = wq[(size_t)cp*128];
            u64 w0 = pk2(w.x,w.x), w1 = pk2(w.y,w.y);
            #pragma unroll
            for (int j = 0; j < NPAIR; j++){
                fma2(acc[0][j], hp[j], w0);
                fma2(acc[1][j], hp[j], w1);
            }
        }
    }

    // Reduce quarters 1..3 into quarter 0, one quarter at a time through sh_buf.
    #pragma unroll
    for (int q = 1; q < 4; q++){
        __syncthreads();                 // previous reads of sh_buf done
        if (kq == q){
            #pragma unroll
            for (int ch = 0; ch < 2; ch++)
                #pragma unroll
                for (int j = 0; j < NPAIR; j++)
                    sh_buf[(oq*2 + ch)*NPAIR + j] = acc[ch][j];
        }
        __syncthreads();
        if (kq == 0){
            #pragma unroll
            for (int ch = 0; ch < 2; ch++)
                #pragma unroll
                for (int j = 0; j < NPAIR; j++){
                    float2 a = up2(acc[ch][j]);
                    float2 b = up2(sh_buf[(oq*2 + ch)*NPAIR + j]);
                    acc[ch][j] = pk2(a.x + b.x, a.y + b.y);
                }
        }
    }

    float s = 0.f, s2 = 0.f;
    float sv[2][VP];
    if (kq == 0){
        #pragma unroll
        for (int ch = 0; ch < 2; ch++){
            float btv = bt[l*Cc + 2*oq + ch];
            #pragma unroll
            for (int j = 0; j < NPAIR; j++){
                float2 a = up2(acc[ch][j]);
                sv[ch][2*j]   = a.x + btv;
                sv[ch][2*j+1] = a.y + btv;
            }
            #pragma unroll
            for (int v = 0; v < Vv; v++){ s += sv[ch][v]; s2 += sv[ch][v]*sv[ch][v]; }
        }
    }
    float2 r = block_reduce_2(s, s2);
    float m    = r.x * (1.f/6400.f);
    float var  = r.y * (1.f/6400.f) - m*m;
    float rstd = rsqrtf(var + 1e-5f);
    if (kq == 0){
        #pragma unroll
        for (int ch = 0; ch < 2; ch++){
            int o = 2*oq + ch;
            const float* w2 = ln2w + l*CV + o*Vv;
            const float* b2 = ln2b + l*CV + o*Vv;
            const float* res = g_Hpad[inbuf] + (t-4)*CVP + o*VP;
            float* Ho = g_Hpad[outbuf] + t*CVP + o*VP;
            #pragma unroll
            for (int v = 0; v < Vv; v++){
                float val = (sv[ch][v] - m)*rstd*w2[v] + b2[v];
                if (t >= 4) val += res[v];
                Ho[v] = fmaxf(val, 0.f);
            }
            Ho[Vv] = 0.f;
        }
    }
}

// ---------------- output head: pool over V + linear ----------------
__global__ void k_out(const float* __restrict__ Wout, const float* __restrict__ bout,
                      float* __restrict__ out, int finbuf){
    __shared__ float pooled[Cc];
    int t = blockIdx.x, tid = threadIdx.x;   // 64 threads
    const float* H = g_Hpad[finbuf] + t*CVP;
    for (int c = tid; c < Cc; c += 64){
        float s = 0.f;
        #pragma unroll
        for (int v = 0; v < Vv; v++) s += H[c*VP + v];
        pooled[c] = s * (1.f/25.f);
    }
    __syncthreads();
    if (tid < NCc){
        float acc = bout[tid];
        const float* wr = Wout + tid*Cc;
        #pragma unroll 8
        for (int c = 0; c < Cc; c++) acc += wr[c]*pooled[c];
        out[t*NCc + tid] = acc;
    }
}

// ---------------- launcher ----------------
extern "C" void kernel_launch(void* const* d_in, const int* in_sizes, int n_in,
                              void* d_out, int out_size){
    const float* x       = (const float*)d_in[0];
    const float* A       = (const float*)d_in[1];
    const float* ln_in_w = (const float*)d_in[2];
    const float* ln_in_b = (const float*)d_in[3];
    const float* W_in    = (const float*)d_in[4];
    const float* b_in    = (const float*)d_in[5];
    const float* Wg      = (const float*)d_in[6];
    const float* bg      = (const float*)d_in[7];
    const float* ln1_w   = (const float*)d_in[8];
    const float* ln1_b   = (const float*)d_in[9];
    const float* Wt      = (const float*)d_in[10];
    const float* bt      = (const float*)d_in[11];
    const float* ln2_w   = (const float*)d_in[12];
    const float* ln2_b   = (const float*)d_in[13];
    const float* imp     = (const float*)d_in[14];
    const float* W_out   = (const float*)d_in[15];
    const float* b_out   = (const float*)d_in[16];
    float* out = (float*)d_out;

    k_prep_wg  <<<512, 256>>>(Wg);
    k_prep_wt  <<<1024,256>>>(Wt);
    k_prep_misc<<<64,  256>>>(A, imp, ln1_b);
    k_in       <<<Tn,  256>>>(x, ln_in_w, ln_in_b, W_in, b_in);

    int inb = 0;
    for (int l = 0; l < Ll; l++){
        k_g1<<<Tn, G1_THREADS>>>(bg, ln1_w, ln1_b, l, inb);
        k_g2<<<Tn, G2_THREADS>>>(bt, ln2_w, ln2_b, l, inb, 1 - inb);
        inb = 1 - inb;
    }
    k_out<<<Tn, 64>>>(W_out, b_out, out, inb);
}

// round 8
// speedup vs baseline: 1.7624x; 1.1036x over previous
#include <cuda_runtime.h>

#define Tn   128
#define Cc   256
#define Kk   3
#define Vv   25
#define VP2  28        // padded V (14 u64 / 7 ulonglong2 pairs, 112B rows)
#define NP64 14        // u64 per row
#define Gg   9
#define Ll   9
#define NCc  60
#define CINn 3
#define CV   (Cc*Vv)    // 6400
#define CV2  (Cc*VP2)   // 7168 floats per timestep
#define U64R (CV2/2)    // 3584 u64 per timestep tile
#define NPAIR 13

typedef unsigned long long u64;

// ---------------- device scratch (static: no allocations allowed) ----------------
__device__ __align__(16) float g_Hpad[2][Tn*CV2];     // ping-pong activations (t, c, VP2)
__device__ __align__(16) float g_Upad[Tn*CV2];        // u_t per layer iteration
__device__ __align__(16) float g_UinitPad[Ll*CV2];    // relu(ln1_b), for t<0
__device__ __align__(16) float g_Al[Ll*Kk*Vv*Vv];     // A * imp
__device__ __align__(16) float g_WgT2[Ll*Cc*Kk*Cc];   // [l][cp][row=k*C+c]
__device__ __align__(16) float g_WtT [Ll*Gg*Cc*Cc];   // [l][g][cp][o]

__device__ __forceinline__ u64 pk2(float lo, float hi){
    return (u64)__float_as_uint(lo) | ((u64)__float_as_uint(hi) << 32);
}
__device__ __forceinline__ float2 up2(u64 v){
    float2 f;
    f.x = __uint_as_float((unsigned)v);
    f.y = __uint_as_float((unsigned)(v >> 32));
    return f;
}
// packed dual-FMA: d = a*b + d
__device__ __forceinline__ void fma2(u64 &d, u64 a, u64 b){
    asm("fma.rn.f32x2 %0, %1, %2, %0;" : "+l"(d) : "l"(a), "l"(b));
}

// block-wide sum of (a,b); up to 16 warps; returns same value to all threads
__device__ __forceinline__ float2 block_reduce_2(float a, float b){
    __shared__ float rA[16], rB[16];
    int lane = threadIdx.x & 31, w = threadIdx.x >> 5;
    #pragma unroll
    for (int o = 16; o; o >>= 1){
        a += __shfl_xor_sync(0xffffffffu, a, o);
        b += __shfl_xor_sync(0xffffffffu, b, o);
    }
    if (lane == 0){ rA[w] = a; rB[w] = b; }
    __syncthreads();
    int nw = blockDim.x >> 5;
    if (w == 0){
        a = (lane < nw) ? rA[lane] : 0.f;
        b = (lane < nw) ? rB[lane] : 0.f;
        #pragma unroll
        for (int o = 8; o; o >>= 1){
            a += __shfl_xor_sync(0xffffffffu, a, o);
            b += __shfl_xor_sync(0xffffffffu, b, o);
        }
        if (lane == 0){ rA[0] = a; rB[0] = b; }
    }
    __syncthreads();
    return make_float2(rA[0], rB[0]);
}

// ---------------- prep kernels ----------------
__global__ void k_prep_wg(const float* __restrict__ Wg){
    int n = Ll*Cc*Kk*Cc;
    for (int d = blockIdx.x*blockDim.x + threadIdx.x; d < n; d += gridDim.x*blockDim.x){
        int l   = d / (Cc*Kk*Cc);
        int r   = d - l*(Cc*Kk*Cc);
        int cp  = r / (Kk*Cc);
        int row = r - cp*(Kk*Cc);
        g_WgT2[d] = Wg[(l*(Kk*Cc) + row)*Cc + cp];
    }
}
__global__ void k_prep_wt(const float* __restrict__ Wt){
    int n = Ll*Gg*Cc*Cc;
    for (int d = blockIdx.x*blockDim.x + threadIdx.x; d < n; d += gridDim.x*blockDim.x){
        int l  = d / (Gg*Cc*Cc);
        int r  = d - l*(Gg*Cc*Cc);
        int g  = r / (Cc*Cc);
        int r2 = r - g*(Cc*Cc);
        int cp = r2 / Cc;
        int o  = r2 - cp*Cc;
        g_WtT[d] = Wt[((l*Cc + o)*Cc + cp)*Gg + g];
    }
}
__global__ void k_prep_misc(const float* __restrict__ A, const float* __restrict__ imp,
                            const float* __restrict__ ln1b){
    int n1 = Ll*Kk*Vv*Vv;
    for (int idx = blockIdx.x*blockDim.x + threadIdx.x; idx < n1; idx += gridDim.x*blockDim.x)
        g_Al[idx] = A[idx % (Kk*Vv*Vv)] * imp[idx];
    int n2 = Ll*CV2;
    for (int idx = blockIdx.x*blockDim.x + threadIdx.x; idx < n2; idx += gridDim.x*blockDim.x){
        int l = idx / CV2;
        int r = idx - l*CV2;
        int c = r / VP2, v = r - c*VP2;
        g_UinitPad[idx] = (v < Vv) ? fmaxf(ln1b[l*CV + c*Vv + v], 0.f) : 0.f;
    }
}

// ---------------- input stage: LN over (CIN,V) + 1x1 conv -> Hpad[0] ----------------
__global__ __launch_bounds__(256,1) void k_in(const float* __restrict__ x,
                                              const float* __restrict__ lnw,
                                              const float* __restrict__ lnb,
                                              const float* __restrict__ Win,
                                              const float* __restrict__ bin){
    __shared__ float sh_xn[CINn*Vv];
    int t = blockIdx.x, tid = threadIdx.x;
    float val = 0.f;
    if (tid < CINn*Vv){
        int cin = tid / Vv, v = tid - cin*Vv;
        val = x[(cin*Tn + t)*Vv + v];
    }
    float2 r = block_reduce_2(val, val*val);
    float m    = r.x * (1.f/75.f);
    float var  = r.y * (1.f/75.f) - m*m;
    float rstd = rsqrtf(var + 1e-5f);
    if (tid < CINn*Vv) sh_xn[tid] = (val - m)*rstd*lnw[tid] + lnb[tid];
    __syncthreads();
    int c = tid;
    float w0 = Win[c*3], w1 = Win[c*3+1], w2 = Win[c*3+2], b = bin[c];
    float* Ho = g_Hpad[0] + t*CV2 + c*VP2;
    #pragma unroll
    for (int v = 0; v < Vv; v++)
        Ho[v] = b + w0*sh_xn[v] + w1*sh_xn[Vv+v] + w2*sh_xn[2*Vv+v];
    Ho[25] = 0.f; Ho[26] = 0.f; Ho[27] = 0.f;
}

// ---------------- stage 1: graph conv + adjacency + LN1 + relu -> Upad ----------------
// 384 threads: kq = tid/192 splits cp in halves of 128; oq = tid%192 owns rows 4oq..4oq+3
// of the 768 (k*C+c) rows. Static smem: sh_buf (h tile, reused as per-k y buffer) + sh_al.
#define G1_THREADS 384

__global__ __launch_bounds__(G1_THREADS,1) void k_g1(const float* __restrict__ bg,
                                                     const float* __restrict__ ln1w,
                                                     const float* __restrict__ ln1b,
                                                     int l, int inbuf){
    __shared__ __align__(16) u64   sh_buf[U64R];        // 3584 u64 = 28,672 B
    __shared__ __align__(16) float sh_al[Kk*Vv*VP2];    // 2100 floats = 8,400 B

    int t = blockIdx.x, tid = threadIdx.x;
    const u64* Hin = (const u64*)(g_Hpad[inbuf] + t*CV2);
    for (int j = tid; j < U64R; j += G1_THREADS) sh_buf[j] = Hin[j];
    const float* Alp = g_Al + l*(Kk*Vv*Vv);
    for (int j = tid; j < Kk*Vv*VP2; j += G1_THREADS){
        int kv = j / VP2, w = j - kv*VP2;
        sh_al[j] = (w < Vv) ? Alp[kv*Vv + w] : 0.f;
    }
    __syncthreads();

    int kq = tid / 192, oq = tid - kq*192;
    u64 acc[4][NPAIR];
    #pragma unroll
    for (int ch = 0; ch < 4; ch++)
        #pragma unroll
        for (int j = 0; j < NPAIR; j++) acc[ch][j] = 0ull;

    const float4* wq = (const float4*)(g_WgT2 + (size_t)(l*Cc + kq*128)*(Kk*Cc)) + oq;
    const ulonglong2* hrow = (const ulonglong2*)(sh_buf + (size_t)(kq*128)*NP64);
    #pragma unroll 2
    for (int cp = 0; cp < 128; cp++){
        ulonglong2 h2[7];
        #pragma unroll
        for (int i = 0; i < 7; i++) h2[i] = hrow[i];
        hrow += 7;
        u64 hp[NPAIR];
        #pragma unroll
        for (int j = 0; j < NPAIR; j++) hp[j] = (j & 1) ? h2[j>>1].y : h2[j>>1].x;
        float4 w = wq[(size_t)cp*192];
        u64 w0 = pk2(w.x,w.x), w1 = pk2(w.y,w.y), w2 = pk2(w.z,w.z), w3 = pk2(w.w,w.w);
        #pragma unroll
        for (int j = 0; j < NPAIR; j++){
            fma2(acc[0][j], hp[j], w0);
            fma2(acc[1][j], hp[j], w1);
            fma2(acc[2][j], hp[j], w2);
            fma2(acc[3][j], hp[j], w3);
        }
    }

    // Per-k batches: combine the two cp-halves of y through sh_buf (reused h region),
    // then apply adjacency for that k into persistent zp registers (threads 0..255).
    int c = tid;             // for adjacency phase
    u64 zp[NPAIR];
    #pragma unroll
    for (int j = 0; j < NPAIR; j++) zp[j] = 0ull;

    #pragma unroll
    for (int k = 0; k < Kk; k++){
        int lo = 64*k, hi = lo + 64;
        __syncthreads();                     // previous phase's reads of sh_buf done
        if (kq == 0 && oq >= lo && oq < hi){
            int cbase = 4*oq - 256*k;
            #pragma unroll
            for (int ch = 0; ch < 4; ch++)
                #pragma unroll
                for (int j = 0; j < NPAIR; j++)
                    sh_buf[(cbase + ch)*NP64 + j] = acc[ch][j];
        }
        __syncthreads();
        if (kq == 1 && oq >= lo && oq < hi){
            int cbase = 4*oq - 256*k;
            #pragma unroll
            for (int ch = 0; ch < 4; ch++)
                #pragma unroll
                for (int j = 0; j < NPAIR; j++){
                    u64* dst = sh_buf + (cbase + ch)*NP64 + j;
                    float2 a = up2(acc[ch][j]), b = up2(*dst);
                    *dst = pk2(a.x + b.x, a.y + b.y);
                }
        }
        __syncthreads();
        if (tid < Cc){
            float bgv = bg[(l*Kk + k)*Cc + c];
            const u64* yrow = sh_buf + c*NP64;
            #pragma unroll
            for (int jp = 0; jp < NPAIR; jp++){
                float2 yy = up2(yrow[jp]);
                int v0 = 2*jp;
                {
                    float yv = yy.x + bgv;
                    u64 yp = pk2(yv, yv);
                    const u64* al = (const u64*)(sh_al + (k*Vv + v0)*VP2);
                    #pragma unroll
                    for (int jw = 0; jw < NPAIR; jw++) fma2(zp[jw], al[jw], yp);
                }
                if (v0 + 1 < Vv){
                    float yv = yy.y + bgv;
                    u64 yp = pk2(yv, yv);
                    const u64* al = (const u64*)(sh_al + (k*Vv + v0 + 1)*VP2);
                    #pragma unroll
                    for (int jw = 0; jw < NPAIR; jw++) fma2(zp[jw], al[jw], yp);
                }
            }
        }
    }

    // LN over (C,V), relu -> Upad
    float s = 0.f, s2 = 0.f;
    float zs[VP2];
    if (tid < Cc){
        #pragma unroll
        for (int j = 0; j < NPAIR; j++){
            float2 zz = up2(zp[j]);
            zs[2*j] = zz.x; zs[2*j+1] = zz.y;
        }
        #pragma unroll
        for (int v = 0; v < Vv; v++){ s += zs[v]; s2 += zs[v]*zs[v]; }
    }
    float2 r = block_reduce_2(s, s2);
    float m    = r.x * (1.f/6400.f);
    float var  = r.y * (1.f/6400.f) - m*m;
    float rstd = rsqrtf(var + 1e-5f);
    if (tid < Cc){
        float* Uo = g_Upad + t*CV2 + c*VP2;
        const float* w1 = ln1w + l*CV + c*Vv;
        const float* b1 = ln1b + l*CV + c*Vv;
        #pragma unroll
        for (int v = 0; v < Vv; v++)
            Uo[v] = fmaxf((zs[v] - m)*rstd*w1[v] + b1[v], 0.f);
        Uo[25] = 0.f; Uo[26] = 0.f; Uo[27] = 0.f;
    }
}

// ---------------- stage 2: temporal conv + LN2 + residual + relu -> Hpad ----------------
// 512 threads: kq = tid>>7 splits cp in quarters of 64; oq = tid&127 owns o = 2oq, 2oq+1.
// U tile staging is software-pipelined: next tile preloaded into 7 regs/thread (3584 = 7*512)
// while computing on the current tile; barrier then cheap STS burst.
#define G2_THREADS 512

__global__ __launch_bounds__(G2_THREADS,1) void k_g2(const float* __restrict__ bt,
                                                     const float* __restrict__ ln2w,
                                                     const float* __restrict__ ln2b,
                                                     int l, int inbuf, int outbuf){
    __shared__ __align__(16) u64 sh_buf[U64R];   // 3584 u64 = 28,672 B

    int t = blockIdx.x, tid = threadIdx.x;
    int kq = tid >> 7, oq = tid & 127;
    u64 acc[2][NPAIR];
    #pragma unroll
    for (int ch = 0; ch < 2; ch++)
        #pragma unroll
        for (int j = 0; j < NPAIR; j++) acc[ch][j] = 0ull;

    // preload tile for g=0
    u64 pre[7];
    {
        const u64* s0 = (t >= 0) ? (const u64*)g_Upad + (size_t)t*U64R
                                 : (const u64*)g_UinitPad + (size_t)l*U64R;
        #pragma unroll
        for (int i = 0; i < 7; i++) pre[i] = s0[tid + i*G2_THREADS];
    }

    for (int g = 0; g < Gg; g++){
        __syncthreads();                      // previous compute's reads of sh_buf done
        #pragma unroll
        for (int i = 0; i < 7; i++) sh_buf[tid + i*G2_THREADS] = pre[i];
        __syncthreads();
        if (g < Gg-1){
            const u64* sn = (t >= g+1) ? (const u64*)g_Upad + (size_t)(t-g-1)*U64R
                                       : (const u64*)g_UinitPad + (size_t)l*U64R;
            #pragma unroll
            for (int i = 0; i < 7; i++) pre[i] = sn[tid + i*G2_THREADS];
        }

        const float2* wq = (const float2*)(g_WtT + (size_t)((l*Gg + g)*Cc + kq*64)*Cc) + oq;
        const ulonglong2* urow = (const ulonglong2*)(sh_buf + (size_t)(kq*64)*NP64);
        #pragma unroll 4
        for (int cp = 0; cp < 64; cp++){
            ulonglong2 h2[7];
            #pragma unroll
            for (int i = 0; i < 7; i++) h2[i] = urow[i];
            urow += 7;
            u64 hp[NPAIR];
            #pragma unroll
            for (int j = 0; j < NPAIR; j++) hp[j] = (j & 1) ? h2[j>>1].y : h2[j>>1].x;
            float2 w = wq[(size_t)cp*128];
            u64 w0 = pk2(w.x,w.x), w1 = pk2(w.y,w.y);
            #pragma unroll
            for (int j = 0; j < NPAIR; j++){
                fma2(acc[0][j], hp[j], w0);
                fma2(acc[1][j], hp[j], w1);
            }
        }
    }

    // Reduce quarters 1..3 into quarter 0, one quarter at a time through sh_buf.
    #pragma unroll
    for (int q = 1; q < 4; q++){
        __syncthreads();                 // previous reads of sh_buf done
        if (kq == q){
            #pragma unroll
            for (int ch = 0; ch < 2; ch++)
                #pragma unroll
                for (int j = 0; j < NPAIR; j++)
                    sh_buf[(oq*2 + ch)*NPAIR + j] = acc[ch][j];
        }
        __syncthreads();
        if (kq == 0){
            #pragma unroll
            for (int ch = 0; ch < 2; ch++)
                #pragma unroll
                for (int j = 0; j < NPAIR; j++){
                    float2 a = up2(acc[ch][j]);
                    float2 b = up2(sh_buf[(oq*2 + ch)*NPAIR + j]);
                    acc[ch][j] = pk2(a.x + b.x, a.y + b.y);
                }
        }
    }

    float s = 0.f, s2 = 0.f;
    float sv[2][VP2];
    if (kq == 0){
        #pragma unroll
        for (int ch = 0; ch < 2; ch++){
            float btv = bt[l*Cc + 2*oq + ch];
            #pragma unroll
            for (int j = 0; j < NPAIR; j++){
                float2 a = up2(acc[ch][j]);
                sv[ch][2*j]   = a.x + btv;
                sv[ch][2*j+1] = a.y + btv;
            }
            #pragma unroll
            for (int v = 0; v < Vv; v++){ s += sv[ch][v]; s2 += sv[ch][v]*sv[ch][v]; }
        }
    }
    float2 r = block_reduce_2(s, s2);
    float m    = r.x * (1.f/6400.f);
    float var  = r.y * (1.f/6400.f) - m*m;
    float rstd = rsqrtf(var + 1e-5f);
    if (kq == 0){
        #pragma unroll
        for (int ch = 0; ch < 2; ch++){
            int o = 2*oq + ch;
            const float* w2 = ln2w + l*CV + o*Vv;
            const float* b2 = ln2b + l*CV + o*Vv;
            const float* res = g_Hpad[inbuf] + (t-4)*CV2 + o*VP2;
            float* Ho = g_Hpad[outbuf] + t*CV2 + o*VP2;
            #pragma unroll
            for (int v = 0; v < Vv; v++){
                float val = (sv[ch][v] - m)*rstd*w2[v] + b2[v];
                if (t >= 4) val += res[v];
                Ho[v] = fmaxf(val, 0.f);
            }
            Ho[25] = 0.f; Ho[26] = 0.f; Ho[27] = 0.f;
        }
    }
}

// ---------------- output head: pool over V + linear ----------------
__global__ void k_out(const float* __restrict__ Wout, const float* __restrict__ bout,
                      float* __restrict__ out, int finbuf){
    __shared__ float pooled[Cc];
    int t = blockIdx.x, tid = threadIdx.x;   // 64 threads
    const float* H = g_Hpad[finbuf] + t*CV2;
    for (int c = tid; c < Cc; c += 64){
        float s = 0.f;
        #pragma unroll
        for (int v = 0; v < Vv; v++) s += H[c*VP2 + v];
        pooled[c] = s * (1.f/25.f);
    }
    __syncthreads();
    if (tid < NCc){
        float acc = bout[tid];
        const float* wr = Wout + tid*Cc;
        #pragma unroll 8
        for (int c = 0; c < Cc; c++) acc += wr[c]*pooled[c];
        out[t*NCc + tid] = acc;
    }
}

// ---------------- launcher ----------------
extern "C" void kernel_launch(void* const* d_in, const int* in_sizes, int n_in,
                              void* d_out, int out_size){
    const float* x       = (const float*)d_in[0];
    const float* A       = (const float*)d_in[1];
    const float* ln_in_w = (const float*)d_in[2];
    const float* ln_in_b = (const float*)d_in[3];
    const float* W_in    = (const float*)d_in[4];
    const float* b_in    = (const float*)d_in[5];
    const float* Wg      = (const float*)d_in[6];
    const float* bg      = (const float*)d_in[7];
    const float* ln1_w   = (const float*)d_in[8];
    const float* ln1_b   = (const float*)d_in[9];
    const float* Wt      = (const float*)d_in[10];
    const float* bt      = (const float*)d_in[11];
    const float* ln2_w   = (const float*)d_in[12];
    const float* ln2_b   = (const float*)d_in[13];
    const float* imp     = (const float*)d_in[14];
    const float* W_out   = (const float*)d_in[15];
    const float* b_out   = (const float*)d_in[16];
    float* out = (float*)d_out;

    k_prep_wg  <<<512, 256>>>(Wg);
    k_prep_wt  <<<1024,256>>>(Wt);
    k_prep_misc<<<64,  256>>>(A, imp, ln1_b);
    k_in       <<<Tn,  256>>>(x, ln_in_w, ln_in_b, W_in, b_in);

    int inb = 0;
    for (int l = 0; l < Ll; l++){
        k_g1<<<Tn, G1_THREADS>>>(bg, ln1_w, ln1_b, l, inb);
        k_g2<<<Tn, G2_THREADS>>>(bt, ln2_w, ln2_b, l, inb, 1 - inb);
        inb = 1 - inb;
    }
    k_out<<<Tn, 64>>>(W_out, b_out, out, inb);
}

// round 10
// speedup vs baseline: 1.9364x; 1.0987x over previous
#include <cuda_runtime.h>

#define Tn   128
#define Cc   256
#define Kk   3
#define Vv   25
#define VP2  28        // padded V (14 u64 / 7 ulonglong2 pairs, 112B rows)
#define NP64 14        // u64 per row
#define Gg   9
#define Ll   9
#define NCc  60
#define CINn 3
#define CV   (Cc*Vv)    // 6400
#define CV2  (Cc*VP2)   // 7168 floats per timestep
#define U64R (CV2/2)    // 3584 u64 per timestep tile
#define NPAIR 13
#define NT   512

typedef unsigned long long u64;

// ---------------- device scratch (static: no allocations allowed) ----------------
__device__ __align__(16) float g_Hpad[2][Tn*CV2];     // input-h of layer l lives in [l&1]
__device__ __align__(16) float g_Upad[2][Tn*CV2];     // U of layer l lives in [l&1]
__device__ __align__(16) float g_UinitPad[Ll*CV2];    // relu(ln1_b), for t<0
__device__ __align__(16) float g_Al[Ll*Kk*Vv*Vv];     // A * imp
__device__ __align__(16) float g_Wg4[Ll*Cc*Cc*4];     // [l][cp][c][k(pad4)]
__device__ __align__(16) float g_WtT[Ll*Gg*Cc*Cc];    // [l][g][cp][o]

__device__ __forceinline__ u64 pk2(float lo, float hi){
    return (u64)__float_as_uint(lo) | ((u64)__float_as_uint(hi) << 32);
}
__device__ __forceinline__ float2 up2(u64 v){
    float2 f;
    f.x = __uint_as_float((unsigned)v);
    f.y = __uint_as_float((unsigned)(v >> 32));
    return f;
}
__device__ __forceinline__ u64 addp(u64 a, u64 b){
    float2 x = up2(a), y = up2(b);
    return pk2(x.x + y.x, x.y + y.y);
}
// packed dual-FMA: d = a*b + d
__device__ __forceinline__ void fma2(u64 &d, u64 a, u64 b){
    asm("fma.rn.f32x2 %0, %1, %2, %0;" : "+l"(d) : "l"(a), "l"(b));
}

// block-wide sum of (a,b); up to 16 warps; returns same value to all threads
__device__ __forceinline__ float2 block_reduce_2(float a, float b){
    __shared__ float rA[16], rB[16];
    int lane = threadIdx.x & 31, w = threadIdx.x >> 5;
    #pragma unroll
    for (int o = 16; o; o >>= 1){
        a += __shfl_xor_sync(0xffffffffu, a, o);
        b += __shfl_xor_sync(0xffffffffu, b, o);
    }
    if (lane == 0){ rA[w] = a; rB[w] = b; }
    __syncthreads();
    int nw = blockDim.x >> 5;
    if (w == 0){
        a = (lane < nw) ? rA[lane] : 0.f;
        b = (lane < nw) ? rB[lane] : 0.f;
        #pragma unroll
        for (int o = 8; o; o >>= 1){
            a += __shfl_xor_sync(0xffffffffu, a, o);
            b += __shfl_xor_sync(0xffffffffu, b, o);
        }
        if (lane == 0){ rA[0] = a; rB[0] = b; }
    }
    __syncthreads();
    return make_float2(rA[0], rB[0]);
}

// ---------------- prep kernels ----------------
__global__ void k_prep_wg4(const float* __restrict__ Wg){
    int n = Ll*Kk*Cc*Cc;
    for (int d = blockIdx.x*blockDim.x + threadIdx.x; d < n; d += gridDim.x*blockDim.x){
        int l   = d / (Kk*Cc*Cc);
        int r   = d - l*(Kk*Cc*Cc);
        int row = r / Cc;          // k*Cc + c
        int cp  = r - row*Cc;
        int kk  = row >> 8;        // k
        int cc  = row & 255;       // c
        g_Wg4[(((size_t)l*Cc + cp)*Cc + cc)*4 + kk] = Wg[d];
    }
}
__global__ void k_prep_wt(const float* __restrict__ Wt){
    int n = Ll*Gg*Cc*Cc;
    for (int d = blockIdx.x*blockDim.x + threadIdx.x; d < n; d += gridDim.x*blockDim.x){
        int l  = d / (Gg*Cc*Cc);
        int r  = d - l*(Gg*Cc*Cc);
        int g  = r / (Cc*Cc);
        int r2 = r - g*(Cc*Cc);
        int cp = r2 / Cc;
        int o  = r2 - cp*Cc;
        g_WtT[d] = Wt[((l*Cc + o)*Cc + cp)*Gg + g];
    }
}
__global__ void k_prep_misc(const float* __restrict__ A, const float* __restrict__ imp,
                            const float* __restrict__ ln1b){
    int n1 = Ll*Kk*Vv*Vv;
    for (int idx = blockIdx.x*blockDim.x + threadIdx.x; idx < n1; idx += gridDim.x*blockDim.x)
        g_Al[idx] = A[idx % (Kk*Vv*Vv)] * imp[idx];
    int n2 = Ll*CV2;
    for (int idx = blockIdx.x*blockDim.x + threadIdx.x; idx < n2; idx += gridDim.x*blockDim.x){
        int l = idx / CV2;
        int r = idx - l*CV2;
        int c = r / VP2, v = r - c*VP2;
        g_UinitPad[idx] = (v < Vv) ? fmaxf(ln1b[l*CV + c*Vv + v], 0.f) : 0.f;
    }
}

// ================= g1 phase (graph conv + adjacency + LN1 + relu -> Upad[lg&1]) =================
// 512 threads: kq = tid>>8 splits cp halves of 128; c = tid&255 owns all 3 k-rows for channel c.
// Expects the layer-input h tile in sh_buf.
__device__ __forceinline__ void g1_phase(int t, int tid, int lg,
                                         u64* sh_buf, const float* sh_al,
                                         const float* __restrict__ bg,
                                         const float* __restrict__ ln1w,
                                         const float* __restrict__ ln1b){
    int kq = tid >> 8, c = tid & 255;
    u64 acc[Kk][NPAIR];
    #pragma unroll
    for (int k = 0; k < Kk; k++)
        #pragma unroll
        for (int j = 0; j < NPAIR; j++) acc[k][j] = 0ull;

    const float4* wg4 = (const float4*)g_Wg4 + (size_t)(lg*Cc + kq*128)*Cc + c;
    const ulonglong2* hrow = (const ulonglong2*)(sh_buf + (size_t)(kq*128)*NP64);
    #pragma unroll 2
    for (int cp = 0; cp < 128; cp++){
        ulonglong2 h2[7];
        #pragma unroll
        for (int i = 0; i < 7; i++) h2[i] = hrow[i];
        hrow += 7;
        u64 hp[NPAIR];
        #pragma unroll
        for (int j = 0; j < NPAIR; j++) hp[j] = (j & 1) ? h2[j>>1].y : h2[j>>1].x;
        float4 w = wg4[(size_t)cp*Cc];
        u64 w0 = pk2(w.x,w.x), w1 = pk2(w.y,w.y), w2 = pk2(w.z,w.z);
        #pragma unroll
        for (int j = 0; j < NPAIR; j++){
            fma2(acc[0][j], hp[j], w0);
            fma2(acc[1][j], hp[j], w1);
            fma2(acc[2][j], hp[j], w2);
        }
    }

    // per-k: combine halves through sh_buf, then adjacency into zp (kq==0 threads)
    u64 zp[NPAIR];
    #pragma unroll
    for (int j = 0; j < NPAIR; j++) zp[j] = 0ull;

    #pragma unroll
    for (int k = 0; k < Kk; k++){
        __syncthreads();
        if (kq == 1){
            #pragma unroll
            for (int j = 0; j < NPAIR; j++) sh_buf[c*NP64 + j] = acc[k][j];
        }
        __syncthreads();
        if (kq == 0){
            #pragma unroll
            for (int j = 0; j < NPAIR; j++) acc[k][j] = addp(acc[k][j], sh_buf[c*NP64 + j]);
            float bgv = bg[(lg*Kk + k)*Cc + c];
            #pragma unroll
            for (int jp = 0; jp < NPAIR; jp++){
                float2 yy = up2(acc[k][jp]);
                int v0 = 2*jp;
                {
                    float yv = yy.x + bgv;
                    u64 yp = pk2(yv, yv);
                    const u64* al = (const u64*)(sh_al + (k*Vv + v0)*VP2);
                    #pragma unroll
                    for (int jw = 0; jw < NPAIR; jw++) fma2(zp[jw], al[jw], yp);
                }
                if (v0 + 1 < Vv){
                    float yv = yy.y + bgv;
                    u64 yp = pk2(yv, yv);
                    const u64* al = (const u64*)(sh_al + (k*Vv + v0 + 1)*VP2);
                    #pragma unroll
                    for (int jw = 0; jw < NPAIR; jw++) fma2(zp[jw], al[jw], yp);
                }
            }
        }
    }

    // LN over (C,V), relu -> Upad[lg&1]
    float s = 0.f, s2 = 0.f;
    float zs[26];
    if (kq == 0){
        #pragma unroll
        for (int j = 0; j < NPAIR; j++){
            float2 zz = up2(zp[j]);
            zs[2*j] = zz.x; zs[2*j+1] = zz.y;
        }
        #pragma unroll
        for (int v = 0; v < Vv; v++){ s += zs[v]; s2 += zs[v]*zs[v]; }
    }
    float2 r = block_reduce_2(s, s2);
    float m    = r.x * (1.f/6400.f);
    float var  = r.y * (1.f/6400.f) - m*m;
    float rstd = rsqrtf(var + 1e-5f);
    if (kq == 0){
        float* Uo = g_Upad[lg & 1] + (size_t)t*CV2 + c*VP2;
        const float* w1 = ln1w + lg*CV + c*Vv;
        const float* b1 = ln1b + lg*CV + c*Vv;
        #pragma unroll
        for (int v = 0; v < Vv; v++)
            Uo[v] = fmaxf((zs[v] - m)*rstd*w1[v] + b1[v], 0.f);
        Uo[25] = 0.f; Uo[26] = 0.f; Uo[27] = 0.f;
    }
}

// ================= g2 phase (temporal conv + LN2 + residual + relu) =================
// 512 threads: kq = tid>>7 quarters of cp (64 each); oq = tid&127 owns o = 2oq, 2oq+1.
// FINAL=false: writes h to g_Hpad[(l+1)&1] and stages h into sh_buf for the g1 phase.
// FINAL=true : pools over V and emits class logits.
template<bool FINAL>
__device__ __forceinline__ void g2_phase(int t, int tid, int l, u64* sh_buf,
                                         const float* __restrict__ bt,
                                         const float* __restrict__ ln2w,
                                         const float* __restrict__ ln2b,
                                         const float* __restrict__ Wout,
                                         const float* __restrict__ bout,
                                         float* __restrict__ out,
                                         float* sh_pool){
    int kq = tid >> 7, oq = tid & 127;
    u64 acc[2][NPAIR];
    #pragma unroll
    for (int ch = 0; ch < 2; ch++)
        #pragma unroll
        for (int j = 0; j < NPAIR; j++) acc[ch][j] = 0ull;

    const u64* Ucur = (const u64*)g_Upad[l & 1];
    const u64* Uini = (const u64*)g_UinitPad + (size_t)l*U64R;

    u64 pre[7];
    {
        const u64* s0 = Ucur + (size_t)t*U64R;
        #pragma unroll
        for (int i = 0; i < 7; i++) pre[i] = s0[tid + i*NT];
    }

    for (int g = 0; g < Gg; g++){
        __syncthreads();
        #pragma unroll
        for (int i = 0; i < 7; i++) sh_buf[tid + i*NT] = pre[i];
        __syncthreads();
        if (g < Gg-1){
            const u64* sn = (t >= g+1) ? Ucur + (size_t)(t-g-1)*U64R : Uini;
            #pragma unroll
            for (int i = 0; i < 7; i++) pre[i] = sn[tid + i*NT];
        }

        const float2* wq = (const float2*)(g_WtT + (size_t)((l*Gg + g)*Cc + kq*64)*Cc) + oq;
        const ulonglong2* urow = (const ulonglong2*)(sh_buf + (size_t)(kq*64)*NP64);
        #pragma unroll 4
        for (int cp = 0; cp < 64; cp++){
            ulonglong2 h2[7];
            #pragma unroll
            for (int i = 0; i < 7; i++) h2[i] = urow[i];
            urow += 7;
            u64 hp[NPAIR];
            #pragma unroll
            for (int j = 0; j < NPAIR; j++) hp[j] = (j & 1) ? h2[j>>1].y : h2[j>>1].x;
            float2 w = wq[(size_t)cp*128];
            u64 w0 = pk2(w.x,w.x), w1 = pk2(w.y,w.y);
            #pragma unroll
            for (int j = 0; j < NPAIR; j++){
                fma2(acc[0][j], hp[j], w0);
                fma2(acc[1][j], hp[j], w1);
            }
        }
    }

    // reduce quarters 1..3 into quarter 0 through sh_buf
    #pragma unroll
    for (int q = 1; q < 4; q++){
        __syncthreads();
        if (kq == q){
            #pragma unroll
            for (int ch = 0; ch < 2; ch++)
                #pragma unroll
                for (int j = 0; j < NPAIR; j++)
                    sh_buf[(oq*2 + ch)*NPAIR + j] = acc[ch][j];
        }
        __syncthreads();
        if (kq == 0){
            #pragma unroll
            for (int ch = 0; ch < 2; ch++)
                #pragma unroll
                for (int j = 0; j < NPAIR; j++)
                    acc[ch][j] = addp(acc[ch][j], sh_buf[(oq*2 + ch)*NPAIR + j]);
        }
    }

    float s = 0.f, s2 = 0.f;
    float sv[2][26];
    if (kq == 0){
        #pragma unroll
        for (int ch = 0; ch < 2; ch++){
            float btv = bt[l*Cc + 2*oq + ch];
            #pragma unroll
            for (int j = 0; j < NPAIR; j++){
                float2 a = up2(acc[ch][j]);
                sv[ch][2*j]   = a.x + btv;
                sv[ch][2*j+1] = a.y + btv;
            }
            #pragma unroll
            for (int v = 0; v < Vv; v++){ s += sv[ch][v]; s2 += sv[ch][v]*sv[ch][v]; }
        }
    }
    float2 r = block_reduce_2(s, s2);
    float m    = r.x * (1.f/6400.f);
    float var  = r.y * (1.f/6400.f) - m*m;
    float rstd = rsqrtf(var + 1e-5f);

    __syncthreads();   // all sh_buf reads done before h restage
    if (kq == 0){
        float* bufF = (float*)sh_buf;
        #pragma unroll
        for (int ch = 0; ch < 2; ch++){
            int o = 2*oq + ch;
            const float* w2 = ln2w + l*CV + o*Vv;
            const float* b2 = ln2b + l*CV + o*Vv;
            const float* res = g_Hpad[l & 1] + (size_t)(t-4)*CV2 + o*VP2;
            if (!FINAL){
                float* Ho = g_Hpad[(l+1) & 1] + (size_t)t*CV2 + o*VP2;
                #pragma unroll
                for (int v = 0; v < Vv; v++){
                    float val = (sv[ch][v] - m)*rstd*w2[v] + b2[v];
                    if (t >= 4) val += res[v];
                    val = fmaxf(val, 0.f);
                    Ho[v] = val;
                    bufF[o*VP2 + v] = val;
                }
                Ho[25] = 0.f; Ho[26] = 0.f; Ho[27] = 0.f;
                bufF[o*VP2 + 25] = 0.f; bufF[o*VP2 + 26] = 0.f; bufF[o*VP2 + 27] = 0.f;
            } else {
                float psum = 0.f;
                #pragma unroll
                for (int v = 0; v < Vv; v++){
                    float val = (sv[ch][v] - m)*rstd*w2[v] + b2[v];
                    if (t >= 4) val += res[v];
                    psum += fmaxf(val, 0.f);
                }
                sh_pool[o] = psum * (1.f/25.f);
            }
        }
    }
    if (FINAL){
        __syncthreads();
        if (tid < NCc){
            float a = bout[tid];
            const float* wr = Wout + tid*Cc;
            #pragma unroll 8
            for (int c = 0; c < Cc; c++) a += wr[c]*sh_pool[c];
            out[t*NCc + tid] = a;
        }
    }
}

// ================= kernels =================
// first: input LN + 1x1 conv + g1 layer 0
__global__ __launch_bounds__(NT,1) void k_first(const float* __restrict__ x,
                                                const float* __restrict__ lnw,
                                                const float* __restrict__ lnb,
                                                const float* __restrict__ Win,
                                                const float* __restrict__ bin,
                                                const float* __restrict__ bg,
                                                const float* __restrict__ ln1w,
                                                const float* __restrict__ ln1b){
    __shared__ __align__(16) u64   sh_buf[U64R];
    __shared__ __align__(16) float sh_al[Kk*Vv*VP2];
    __shared__ float sh_xn[CINn*Vv];
    int t = blockIdx.x, tid = threadIdx.x;

    const float* Alp = g_Al;   // layer 0
    for (int j = tid; j < Kk*Vv*VP2; j += NT){
        int kv = j / VP2, w = j - kv*VP2;
        sh_al[j] = (w < Vv) ? Alp[kv*Vv + w] : 0.f;
    }

    float val = 0.f;
    if (tid < CINn*Vv){
        int cin = tid / Vv, v = tid - cin*Vv;
        val = x[(cin*Tn + t)*Vv + v];
    }
    float2 r = block_reduce_2(val, val*val);
    float m    = r.x * (1.f/75.f);
    float var  = r.y * (1.f/75.f) - m*m;
    float rstd = rsqrtf(var + 1e-5f);
    if (tid < CINn*Vv) sh_xn[tid] = (val - m)*rstd*lnw[tid] + lnb[tid];
    __syncthreads();

    if (tid < Cc){
        int c = tid;
        float w0 = Win[c*3], w1 = Win[c*3+1], w2 = Win[c*3+2], b = bin[c];
        float* Ho = g_Hpad[0] + (size_t)t*CV2 + c*VP2;
        float* bufF = (float*)sh_buf;
        #pragma unroll
        for (int v = 0; v < Vv; v++){
            float h = b + w0*sh_xn[v] + w1*sh_xn[Vv+v] + w2*sh_xn[2*Vv+v];
            Ho[v] = h;
            bufF[c*VP2 + v] = h;
        }
        Ho[25] = 0.f; Ho[26] = 0.f; Ho[27] = 0.f;
        bufF[c*VP2 + 25] = 0.f; bufF[c*VP2 + 26] = 0.f; bufF[c*VP2 + 27] = 0.f;
    }
    __syncthreads();

    g1_phase(t, tid, 0, sh_buf, sh_al, bg, ln1w, ln1b);
}

// fused: g2 of layer l + g1 of layer l+1
__global__ __launch_bounds__(NT,1) void k_fuse(const float* __restrict__ bt,
                                               const float* __restrict__ ln2w,
                                               const float* __restrict__ ln2b,
                                               const float* __restrict__ bg,
                                               const float* __restrict__ ln1w,
                                               const float* __restrict__ ln1b,
                                               int l){
    __shared__ __align__(16) u64   sh_buf[U64R];
    __shared__ __align__(16) float sh_al[Kk*Vv*VP2];
    int t = blockIdx.x, tid = threadIdx.x;
    int lg = l + 1;

    const float* Alp = g_Al + lg*(Kk*Vv*Vv);
    for (int j = tid; j < Kk*Vv*VP2; j += NT){
        int kv = j / VP2, w = j - kv*VP2;
        sh_al[j] = (w < Vv) ? Alp[kv*Vv + w] : 0.f;
    }
    // no explicit sync needed here: g2_phase begins with __syncthreads()
    // (sh_al is not touched by g2_phase, and every thread writes/reads sh_al
    //  only after that barrier)

    g2_phase<false>(t, tid, l, sh_buf, bt, ln2w, ln2b, nullptr, nullptr, nullptr, nullptr);
    __syncthreads();
    g1_phase(t, tid, lg, sh_buf, sh_al, bg, ln1w, ln1b);
}

// final: g2 of layer 8 + pooling + head
__global__ __launch_bounds__(NT,1) void k_fin(const float* __restrict__ bt,
                                              const float* __restrict__ ln2w,
                                              const float* __restrict__ ln2b,
                                              const float* __restrict__ Wout,
                                              const float* __restrict__ bout,
                                              float* __restrict__ out){
    __shared__ __align__(16) u64 sh_buf[U64R];
    __shared__ float sh_pool[Cc];
    int t = blockIdx.x, tid = threadIdx.x;
    g2_phase<true>(t, tid, Ll-1, sh_buf, bt, ln2w, ln2b, Wout, bout, out, sh_pool);
}

// ---------------- launcher ----------------
extern "C" void kernel_launch(void* const* d_in, const int* in_sizes, int n_in,
                              void* d_out, int out_size){
    const float* x       = (const float*)d_in[0];
    const float* A       = (const float*)d_in[1];
    const float* ln_in_w = (const float*)d_in[2];
    const float* ln_in_b = (const float*)d_in[3];
    const float* W_in    = (const float*)d_in[4];
    const float* b_in    = (const float*)d_in[5];
    const float* Wg      = (const float*)d_in[6];
    const float* bg      = (const float*)d_in[7];
    const float* ln1_w   = (const float*)d_in[8];
    const float* ln1_b   = (const float*)d_in[9];
    const float* Wt      = (const float*)d_in[10];
    const float* bt      = (const float*)d_in[11];
    const float* ln2_w   = (const float*)d_in[12];
    const float* ln2_b   = (const float*)d_in[13];
    const float* imp     = (const float*)d_in[14];
    const float* W_out   = (const float*)d_in[15];
    const float* b_out   = (const float*)d_in[16];
    float* out = (float*)d_out;

    k_prep_wg4 <<<512, 256>>>(Wg);
    k_prep_wt  <<<1024,256>>>(Wt);
    k_prep_misc<<<64,  256>>>(A, imp, ln1_b);

    k_first<<<Tn, NT>>>(x, ln_in_w, ln_in_b, W_in, b_in, bg, ln1_w, ln1_b);
    for (int l = 0; l < Ll-1; l++)
        k_fuse<<<Tn, NT>>>(bt, ln2_w, ln2_b, bg, ln1_w, ln1_b, l);
    k_fin<<<Tn, NT>>>(bt, ln2_w, ln2_b, W_out, b_out, out);
}